// round 11
// baseline (speedup 1.0000x reference)
#include <cuda_runtime.h>
#include <cuda_bf16.h>
#include <cuda_fp8.h>
#include <math.h>
#include <stdint.h>

// NTXent — Round 11: FP8 (e4m3) mma.sync m16n8k32 GEMM for sum-exp;
// operands pre-normalized, scaled by 16, quantized to e4m3 (dot = 256*S).
// R8 skeleton: 128x128 CTA, 4 warps of 64x64, 3-stage cp.async (wait_group 1).
// diag & row-sums via exact fp32 rank-1 side paths. qsum fused into prep.

#define B_SIZE 8192
#define D_SIZE 626
#define KPAD   640
#define FP8_SCALE 16.0f
#define EXP_SCALE (4.0f / (FP8_SCALE * FP8_SCALE))   // 0.015625

#define BM 128
#define BN 128
#define BK 64                          // k elements per stage (fp8)
#define NITER (KPAD / BK)              // 10
#define STAGES 3
#define ROWB 80                        // 64 fp8 bytes + 16B pad
#define STAGE_BYTES (2 * BM * ROWB)    // 20480
#define SMEM_BYTES (STAGES * STAGE_BYTES)   // 61440

// ---------------- persistent scratch ---------------------------------------
__device__ __align__(128) uint8_t g_Ab[B_SIZE * KPAD];   // e4m3(16*a_hat)
__device__ __align__(128) uint8_t g_Pb[B_SIZE * KPAD];   // e4m3(16*p_hat)
__device__ float g_rna[B_SIZE];
__device__ float g_sumexp[B_SIZE];
__device__ float g_sumS[B_SIZE];
__device__ float g_diag[B_SIZE];
__device__ float g_q[D_SIZE];

// ---------------- helpers ---------------------------------------------------
__device__ __forceinline__ uint32_t smem_u32(const void* p) {
    uint32_t a;
    asm("{ .reg .u64 t; cvta.to.shared.u64 t, %1; cvt.u32.u64 %0, t; }"
        : "=r"(a) : "l"(p));
    return a;
}
__device__ __forceinline__ void cp16(uint32_t dst, const void* src) {
    asm volatile("cp.async.cg.shared.global [%0], [%1], 16;" :: "r"(dst), "l"(src));
}
__device__ __forceinline__ void ldsm_x4(uint32_t* r, uint32_t addr) {
    asm volatile("ldmatrix.sync.aligned.m8n8.x4.shared.b16 {%0,%1,%2,%3}, [%4];"
                 : "=r"(r[0]), "=r"(r[1]), "=r"(r[2]), "=r"(r[3]) : "r"(addr));
}
__device__ __forceinline__ void mma_e4m3(float* c, const uint32_t* a,
                                         uint32_t b0, uint32_t b1) {
    asm volatile(
        "mma.sync.aligned.m16n8k32.row.col.f32.e4m3.e4m3.f32 "
        "{%0,%1,%2,%3}, {%4,%5,%6,%7}, {%8,%9}, {%0,%1,%2,%3};"
        : "+f"(c[0]), "+f"(c[1]), "+f"(c[2]), "+f"(c[3])
        : "r"(a[0]), "r"(a[1]), "r"(a[2]), "r"(a[3]), "r"(b0), "r"(b1));
}

// ---------------------------------------------------------------------------
// prep: norms, exact fp32 diag, fp8 normalized copies (x16), fused q accum
// ---------------------------------------------------------------------------
__global__ void __launch_bounds__(256) ntxent_prep(const float* __restrict__ A,
                                                   const float* __restrict__ P,
                                                   float* __restrict__ out) {
    __shared__ float qacc[D_SIZE];
    for (int c = threadIdx.x; c < D_SIZE; c += 256) qacc[c] = 0.f;
    __syncthreads();

    const int warp = threadIdx.x >> 5;
    const int lane = threadIdx.x & 31;
    const int row  = blockIdx.x * 8 + warp;

    const float* ar = A + (size_t)row * D_SIZE;
    const float* pr = P + (size_t)row * D_SIZE;
    float ssa = 0.f, ssp = 0.f, dot = 0.f;
    for (int c = lane; c < D_SIZE; c += 32) {
        float av = ar[c], pv = pr[c];
        ssa = fmaf(av, av, ssa);
        ssp = fmaf(pv, pv, ssp);
        dot = fmaf(av, pv, dot);
    }
    #pragma unroll
    for (int o = 16; o; o >>= 1) {
        ssa += __shfl_xor_sync(0xffffffffu, ssa, o);
        ssp += __shfl_xor_sync(0xffffffffu, ssp, o);
        dot += __shfl_xor_sync(0xffffffffu, dot, o);
    }
    const float rna = rsqrtf(ssa);
    const float rnp = rsqrtf(ssp);

    uint8_t* ya = g_Ab + (size_t)row * KPAD;
    uint8_t* yp = g_Pb + (size_t)row * KPAD;
    for (int c = lane; c < KPAD; c += 32) {
        float av = (c < D_SIZE) ? ar[c] * rna : 0.f;
        float pv = (c < D_SIZE) ? pr[c] * rnp : 0.f;
        ya[c] = (uint8_t)__nv_cvt_float_to_fp8(av * FP8_SCALE, __NV_SATFINITE, __NV_E4M3);
        yp[c] = (uint8_t)__nv_cvt_float_to_fp8(pv * FP8_SCALE, __NV_SATFINITE, __NV_E4M3);
        if (c < D_SIZE) atomicAdd(&qacc[c], pv);
    }
    if (lane == 0) {
        g_rna[row]    = rna;
        g_diag[row]   = dot * rna * rnp;
        g_sumexp[row] = 0.f;
    }
    __syncthreads();
    for (int c = threadIdx.x; c < D_SIZE; c += 256)
        atomicAdd(&g_q[c], qacc[c]);
    if (blockIdx.x == 0 && threadIdx.x < 3) out[threadIdx.x] = 0.f;
}

__global__ void ntxent_zeroq() {
    if (threadIdx.x < D_SIZE) g_q[threadIdx.x] = 0.f;
}

// ---------------------------------------------------------------------------
// rowsum: g_sumS[i] = rna[i] * (A[i] . q)   (exact fp32)
// ---------------------------------------------------------------------------
__global__ void __launch_bounds__(256) ntxent_rowsum(const float* __restrict__ A) {
    const int warp = threadIdx.x >> 5;
    const int lane = threadIdx.x & 31;
    const int row  = blockIdx.x * 8 + warp;

    const float* ar = A + (size_t)row * D_SIZE;
    float d = 0.f;
    for (int c = lane; c < D_SIZE; c += 32)
        d = fmaf(ar[c], g_q[c], d);
    #pragma unroll
    for (int o = 16; o; o >>= 1) d += __shfl_xor_sync(0xffffffffu, d, o);
    if (lane == 0) g_sumS[row] = d * g_rna[row];
}

// ---------------------------------------------------------------------------
// stage loader (128 threads): 128x64B A + 128x64B B fp8, 16B cp.async each
// ---------------------------------------------------------------------------
__device__ __forceinline__ void load_stage(uint32_t sbase, int m0, int n0,
                                           int k0, int tid) {
    const char* asrc = (const char*)g_Ab + (size_t)m0 * KPAD + k0;
    const char* bsrc = (const char*)g_Pb + (size_t)n0 * KPAD + k0;
    #pragma unroll
    for (int i = 0; i < 4; i++) {
        int seg = tid + i * 128, row = seg >> 2, g = seg & 3;
        cp16(sbase + row * ROWB + g * 16, asrc + (size_t)row * KPAD + g * 16);
    }
    #pragma unroll
    for (int i = 0; i < 4; i++) {
        int seg = tid + i * 128, row = seg >> 2, g = seg & 3;
        cp16(sbase + BM * ROWB + row * ROWB + g * 16,
             bsrc + (size_t)row * KPAD + g * 16);
    }
    asm volatile("cp.async.commit_group;" ::: "memory");
}

// ---------------------------------------------------------------------------
// main: 128x128 tile, 4 warps (64x64), fp8 k32 MMA, BK=64, 3-stage pipeline
// ---------------------------------------------------------------------------
__global__ void __launch_bounds__(128) ntxent_hmma() {
    extern __shared__ char smem[];
    const uint32_t sbase = smem_u32(smem);

    const int tid  = threadIdx.x;
    const int lane = tid & 31;
    const int wid  = tid >> 5;
    const int wm   = wid >> 1;
    const int wn   = wid & 1;
    const int m0   = blockIdx.y * BM;
    const int n0   = blockIdx.x * BN;

    float acc[4][8][4];
    #pragma unroll
    for (int i = 0; i < 4; i++)
        #pragma unroll
        for (int j = 0; j < 8; j++)
            #pragma unroll
            for (int q = 0; q < 4; q++) acc[i][j][q] = 0.f;

    // ldmatrix addressing (byte-identical pattern to bf16 k16 case):
    // A x4: row = lane%16, k-half(16B) = lane/16
    // B x4 (two n-tiles): n = (lane&7) + ((lane&16)>>1), k-half = (lane>>3)&1
    const int a_row  = lane & 15;
    const int a_koff = ((lane >> 4) & 1) * 16;
    const int b_n    = (lane & 7) | ((lane >> 1) & 8);
    const int b_koff = ((lane >> 3) & 1) * 16;
    const uint32_t aBase = sbase + (wm * 64 + a_row) * ROWB + a_koff;
    const uint32_t bBase = sbase + BM * ROWB + (wn * 64 + b_n) * ROWB + b_koff;

    load_stage(sbase,               m0, n0, 0,  tid);
    load_stage(sbase + STAGE_BYTES, m0, n0, BK, tid);

    uint32_t soff = 0;
    uint32_t loff = 2 * STAGE_BYTES;
    int      lk   = 2 * BK;

    for (int c = 0; c < NITER; c++) {
        if (c < NITER - 1) asm volatile("cp.async.wait_group 1;" ::: "memory");
        else               asm volatile("cp.async.wait_group 0;" ::: "memory");
        __syncthreads();

        #pragma unroll
        for (int ks = 0; ks < 2; ks++) {          // two k32 steps per stage
            const uint32_t koff = soff + ks * 32; // 32 bytes = k32 fp8

            uint32_t afrag[4][4];
            #pragma unroll
            for (int mi = 0; mi < 4; mi++)
                ldsm_x4(afrag[mi], aBase + koff + mi * (16 * ROWB));

            uint32_t bfrag[4][4];                 // [n-tile-pair][4 regs]
            #pragma unroll
            for (int p = 0; p < 4; p++)
                ldsm_x4(bfrag[p], bBase + koff + p * (16 * ROWB));

            #pragma unroll
            for (int mi = 0; mi < 4; mi++)
                #pragma unroll
                for (int p = 0; p < 4; p++) {
                    mma_e4m3(acc[mi][p * 2 + 0], afrag[mi],
                             bfrag[p][0], bfrag[p][1]);
                    mma_e4m3(acc[mi][p * 2 + 1], afrag[mi],
                             bfrag[p][2], bfrag[p][3]);
                }
        }

        if (c + 2 < NITER) {
            load_stage(sbase + loff, m0, n0, lk, tid);
            lk += BK;
            loff += STAGE_BYTES;
            if (loff == STAGES * STAGE_BYTES) loff = 0;
        }
        soff += STAGE_BYTES;
        if (soff == STAGES * STAGE_BYTES) soff = 0;
    }

    // ---- epilogue: per-row sum of exp(4*S) = exp(acc * EXP_SCALE) ----
    float esum[8];
    #pragma unroll
    for (int q = 0; q < 8; q++) esum[q] = 0.f;

    #pragma unroll
    for (int mi = 0; mi < 4; mi++)
        #pragma unroll
        for (int nt = 0; nt < 8; nt++) {
            const float* cc = acc[mi][nt];
            esum[mi * 2 + 0] += __expf(EXP_SCALE * cc[0]) + __expf(EXP_SCALE * cc[1]);
            esum[mi * 2 + 1] += __expf(EXP_SCALE * cc[2]) + __expf(EXP_SCALE * cc[3]);
        }
    #pragma unroll
    for (int q = 0; q < 8; q++)
        #pragma unroll
        for (int o = 1; o < 4; o <<= 1)
            esum[q] += __shfl_xor_sync(0xffffffffu, esum[q], o);
    if ((lane & 3) == 0) {
        #pragma unroll
        for (int q = 0; q < 8; q++) {
            const int row = m0 + wm * 64 + (q >> 1) * 16 + (q & 1) * 8 + (lane >> 2);
            atomicAdd(&g_sumexp[row], esum[q]);
        }
    }
}

// ---------------------------------------------------------------------------
// finalize
// ---------------------------------------------------------------------------
__global__ void __launch_bounds__(256) ntxent_finalize(float* __restrict__ out) {
    const int i = blockIdx.x * 256 + threadIdx.x;
    const int lane = threadIdx.x & 31;
    const int warp = threadIdx.x >> 5;

    const float d = g_diag[i];
    float loss = logf(g_sumexp[i]) - 4.0f * d;
    float pos  = d;
    float neg  = (g_sumS[i] - d) * (1.0f / (float)(B_SIZE - 1));

    #pragma unroll
    for (int off = 16; off; off >>= 1) {
        loss += __shfl_down_sync(0xffffffffu, loss, off);
        pos  += __shfl_down_sync(0xffffffffu, pos,  off);
        neg  += __shfl_down_sync(0xffffffffu, neg,  off);
    }
    __shared__ float sl[8], sp[8], sn[8];
    if (lane == 0) { sl[warp] = loss; sp[warp] = pos; sn[warp] = neg; }
    __syncthreads();
    if (threadIdx.x == 0) {
        float tl = 0.f, tp = 0.f, tg = 0.f;
        #pragma unroll
        for (int w = 0; w < 8; w++) { tl += sl[w]; tp += sp[w]; tg += sn[w]; }
        const float invB = 1.0f / (float)B_SIZE;
        atomicAdd(out + 0, tl * invB);
        atomicAdd(out + 1, tp * invB);
        atomicAdd(out + 2, tg * invB);
    }
}

// ---------------------------------------------------------------------------
extern "C" void kernel_launch(void* const* d_in, const int* in_sizes, int n_in,
                              void* d_out, int out_size) {
    const float* A = (const float*)d_in[0];
    const float* P = (const float*)d_in[1];
    float* out = (float*)d_out;

    cudaFuncSetAttribute(ntxent_hmma,
                         cudaFuncAttributeMaxDynamicSharedMemorySize, SMEM_BYTES);

    ntxent_zeroq<<<1, 1024>>>();
    ntxent_prep<<<B_SIZE / 8, 256>>>(A, P, out);
    ntxent_rowsum<<<B_SIZE / 8, 256>>>(A);

    dim3 gg(B_SIZE / BN, B_SIZE / BM);   // (64, 64)
    ntxent_hmma<<<gg, 128, SMEM_BYTES>>>();

    ntxent_finalize<<<B_SIZE / 256, 256>>>(out);
}

// round 12
// speedup vs baseline: 1.0962x; 1.0962x over previous
#include <cuda_runtime.h>
#include <cuda_bf16.h>
#include <math.h>
#include <stdint.h>

// NTXent — Round 12: R8 GEMM config (128x128 CTA, 4 warps of 64x64, BK=32,
// 3-stage cp.async wait_group 1) with refill issued BEFORE compute (extra
// iteration of load slack), fused qsum prep. bf16 mma.sync computes only
// sum_j exp(4*S_ij); diag & row-sums via exact fp32 rank-1 side paths.

#define B_SIZE 8192
#define D_SIZE 626
#define KPAD   640
#define INV_TEMP 4.0f

#define BM 128
#define BN 128
#define BK 32
#define NITER (KPAD / BK)             // 20
#define STAGES 3
#define ROWB 80                        // 32 bf16 + 8B pad
#define STAGE_BYTES (2 * BM * ROWB)    // 20480
#define SMEM_BYTES (STAGES * STAGE_BYTES)   // 61440

// ---------------- persistent scratch ---------------------------------------
__device__ __align__(128) __nv_bfloat16 g_Ab[B_SIZE * KPAD];
__device__ __align__(128) __nv_bfloat16 g_Pb[B_SIZE * KPAD];
__device__ float g_rna[B_SIZE];
__device__ float g_sumexp[B_SIZE];
__device__ float g_sumS[B_SIZE];
__device__ float g_diag[B_SIZE];
__device__ float g_q[D_SIZE];

// ---------------- helpers ---------------------------------------------------
__device__ __forceinline__ uint32_t smem_u32(const void* p) {
    uint32_t a;
    asm("{ .reg .u64 t; cvta.to.shared.u64 t, %1; cvt.u32.u64 %0, t; }"
        : "=r"(a) : "l"(p));
    return a;
}
__device__ __forceinline__ void cp16(uint32_t dst, const void* src) {
    asm volatile("cp.async.cg.shared.global [%0], [%1], 16;" :: "r"(dst), "l"(src));
}
__device__ __forceinline__ void ldsm_x4(uint32_t* r, uint32_t addr) {
    asm volatile("ldmatrix.sync.aligned.m8n8.x4.shared.b16 {%0,%1,%2,%3}, [%4];"
                 : "=r"(r[0]), "=r"(r[1]), "=r"(r[2]), "=r"(r[3]) : "r"(addr));
}
__device__ __forceinline__ void mma_bf16(float* c, const uint32_t* a,
                                         uint32_t b0, uint32_t b1) {
    asm volatile(
        "mma.sync.aligned.m16n8k16.row.col.f32.bf16.bf16.f32 "
        "{%0,%1,%2,%3}, {%4,%5,%6,%7}, {%8,%9}, {%0,%1,%2,%3};"
        : "+f"(c[0]), "+f"(c[1]), "+f"(c[2]), "+f"(c[3])
        : "r"(a[0]), "r"(a[1]), "r"(a[2]), "r"(a[3]), "r"(b0), "r"(b1));
}

// ---------------------------------------------------------------------------
// prep: norms, exact fp32 diag, normalized bf16 copies, fused q accumulation
// ---------------------------------------------------------------------------
__global__ void __launch_bounds__(256) ntxent_prep(const float* __restrict__ A,
                                                   const float* __restrict__ P,
                                                   float* __restrict__ out) {
    __shared__ float qacc[D_SIZE];
    for (int c = threadIdx.x; c < D_SIZE; c += 256) qacc[c] = 0.f;
    __syncthreads();

    const int warp = threadIdx.x >> 5;
    const int lane = threadIdx.x & 31;
    const int row  = blockIdx.x * 8 + warp;

    const float* ar = A + (size_t)row * D_SIZE;
    const float* pr = P + (size_t)row * D_SIZE;
    float ssa = 0.f, ssp = 0.f, dot = 0.f;
    for (int c = lane; c < D_SIZE; c += 32) {
        float av = ar[c], pv = pr[c];
        ssa = fmaf(av, av, ssa);
        ssp = fmaf(pv, pv, ssp);
        dot = fmaf(av, pv, dot);
    }
    #pragma unroll
    for (int o = 16; o; o >>= 1) {
        ssa += __shfl_xor_sync(0xffffffffu, ssa, o);
        ssp += __shfl_xor_sync(0xffffffffu, ssp, o);
        dot += __shfl_xor_sync(0xffffffffu, dot, o);
    }
    const float rna = rsqrtf(ssa);
    const float rnp = rsqrtf(ssp);

    __nv_bfloat16* ya = g_Ab + (size_t)row * KPAD;
    __nv_bfloat16* yp = g_Pb + (size_t)row * KPAD;
    for (int c = lane; c < KPAD; c += 32) {
        float av = (c < D_SIZE) ? ar[c] * rna : 0.f;
        float pv = (c < D_SIZE) ? pr[c] * rnp : 0.f;
        ya[c] = __float2bfloat16(av);
        yp[c] = __float2bfloat16(pv);
        if (c < D_SIZE) atomicAdd(&qacc[c], pv);
    }
    if (lane == 0) {
        g_rna[row]    = rna;
        g_diag[row]   = dot * rna * rnp;
        g_sumexp[row] = 0.f;
    }
    __syncthreads();
    for (int c = threadIdx.x; c < D_SIZE; c += 256)
        atomicAdd(&g_q[c], qacc[c]);
    if (blockIdx.x == 0 && threadIdx.x < 3) out[threadIdx.x] = 0.f;
}

__global__ void ntxent_zeroq() {
    if (threadIdx.x < D_SIZE) g_q[threadIdx.x] = 0.f;
}

// ---------------------------------------------------------------------------
// rowsum: g_sumS[i] = rna[i] * (A[i] . q)
// ---------------------------------------------------------------------------
__global__ void __launch_bounds__(256) ntxent_rowsum(const float* __restrict__ A) {
    const int warp = threadIdx.x >> 5;
    const int lane = threadIdx.x & 31;
    const int row  = blockIdx.x * 8 + warp;

    const float* ar = A + (size_t)row * D_SIZE;
    float d = 0.f;
    for (int c = lane; c < D_SIZE; c += 32)
        d = fmaf(ar[c], g_q[c], d);
    #pragma unroll
    for (int o = 16; o; o >>= 1) d += __shfl_xor_sync(0xffffffffu, d, o);
    if (lane == 0) g_sumS[row] = d * g_rna[row];
}

// ---------------------------------------------------------------------------
// stage loader (128 threads): 128x32 A + 128x32 B bf16, 16B cp.async each
// ---------------------------------------------------------------------------
__device__ __forceinline__ void load_stage(uint32_t sbase, int m0, int n0,
                                           int k0, int tid) {
    const char* asrc = (const char*)g_Ab + ((size_t)m0 * KPAD + k0) * 2;
    const char* bsrc = (const char*)g_Pb + ((size_t)n0 * KPAD + k0) * 2;
    #pragma unroll
    for (int i = 0; i < 4; i++) {
        int seg = tid + i * 128, row = seg >> 2, g = seg & 3;
        cp16(sbase + row * ROWB + g * 16, asrc + (size_t)row * (KPAD * 2) + g * 16);
    }
    #pragma unroll
    for (int i = 0; i < 4; i++) {
        int seg = tid + i * 128, row = seg >> 2, g = seg & 3;
        cp16(sbase + BM * ROWB + row * ROWB + g * 16,
             bsrc + (size_t)row * (KPAD * 2) + g * 16);
    }
    asm volatile("cp.async.commit_group;" ::: "memory");
}

// ---------------------------------------------------------------------------
// main: 128x128 tile, 4 warps (64x64), BK=32, 3-stage (wait_group 1),
// refill issued BEFORE compute
// ---------------------------------------------------------------------------
__global__ void __launch_bounds__(128) ntxent_hmma() {
    extern __shared__ char smem[];
    const uint32_t sbase = smem_u32(smem);

    const int tid  = threadIdx.x;
    const int lane = tid & 31;
    const int wid  = tid >> 5;
    const int wm   = wid >> 1;
    const int wn   = wid & 1;
    const int m0   = blockIdx.y * BM;
    const int n0   = blockIdx.x * BN;

    float acc[4][8][4];
    #pragma unroll
    for (int i = 0; i < 4; i++)
        #pragma unroll
        for (int j = 0; j < 8; j++)
            #pragma unroll
            for (int q = 0; q < 4; q++) acc[i][j][q] = 0.f;

    const int a_row  = lane & 15;
    const int a_koff = ((lane >> 4) & 1) * 16;
    const int b_n    = (lane & 7) | ((lane >> 1) & 8);
    const int b_koff = ((lane >> 3) & 1) * 16;
    const uint32_t aBase = sbase + (wm * 64 + a_row) * ROWB + a_koff;
    const uint32_t bBase = sbase + BM * ROWB + (wn * 64 + b_n) * ROWB + b_koff;

    load_stage(sbase,               m0, n0, 0,  tid);
    load_stage(sbase + STAGE_BYTES, m0, n0, BK, tid);

    uint32_t soff = 0;
    uint32_t loff = 2 * STAGE_BYTES;
    int      lk   = 2 * BK;

    for (int c = 0; c < NITER; c++) {
        if (c < NITER - 1) asm volatile("cp.async.wait_group 1;" ::: "memory");
        else               asm volatile("cp.async.wait_group 0;" ::: "memory");
        __syncthreads();

        // refill FIRST: stage (c-1)%3 was fully consumed before the barrier;
        // issuing here gives the load ~2 compute blocks of slack.
        if (c + 2 < NITER) {
            load_stage(sbase + loff, m0, n0, lk, tid);
            lk += BK;
            loff += STAGE_BYTES;
            if (loff == STAGES * STAGE_BYTES) loff = 0;
        }

        #pragma unroll
        for (int ks = 0; ks < 2; ks++) {
            const uint32_t koff = soff + ks * 32;

            uint32_t afrag[4][4];
            #pragma unroll
            for (int mi = 0; mi < 4; mi++)
                ldsm_x4(afrag[mi], aBase + koff + mi * (16 * ROWB));

            uint32_t bfrag[4][4];
            #pragma unroll
            for (int np = 0; np < 4; np++)
                ldsm_x4(bfrag[np], bBase + koff + np * (16 * ROWB));

            #pragma unroll
            for (int mi = 0; mi < 4; mi++)
                #pragma unroll
                for (int np = 0; np < 4; np++) {
                    mma_bf16(acc[mi][np * 2 + 0], afrag[mi],
                             bfrag[np][0], bfrag[np][1]);
                    mma_bf16(acc[mi][np * 2 + 1], afrag[mi],
                             bfrag[np][2], bfrag[np][3]);
                }
        }

        soff += STAGE_BYTES;
        if (soff == STAGES * STAGE_BYTES) soff = 0;
    }

    // ---- epilogue: per-row sum of exp(4*S) ----
    float esum[8];
    #pragma unroll
    for (int q = 0; q < 8; q++) esum[q] = 0.f;

    #pragma unroll
    for (int mi = 0; mi < 4; mi++)
        #pragma unroll
        for (int nt = 0; nt < 8; nt++) {
            const float* cc = acc[mi][nt];
            esum[mi * 2 + 0] += __expf(INV_TEMP * cc[0]) + __expf(INV_TEMP * cc[1]);
            esum[mi * 2 + 1] += __expf(INV_TEMP * cc[2]) + __expf(INV_TEMP * cc[3]);
        }
    #pragma unroll
    for (int q = 0; q < 8; q++)
        #pragma unroll
        for (int o = 1; o < 4; o <<= 1)
            esum[q] += __shfl_xor_sync(0xffffffffu, esum[q], o);
    if ((lane & 3) == 0) {
        #pragma unroll
        for (int q = 0; q < 8; q++) {
            const int row = m0 + wm * 64 + (q >> 1) * 16 + (q & 1) * 8 + (lane >> 2);
            atomicAdd(&g_sumexp[row], esum[q]);
        }
    }
}

// ---------------------------------------------------------------------------
// finalize
// ---------------------------------------------------------------------------
__global__ void __launch_bounds__(256) ntxent_finalize(float* __restrict__ out) {
    const int i = blockIdx.x * 256 + threadIdx.x;
    const int lane = threadIdx.x & 31;
    const int warp = threadIdx.x >> 5;

    const float d = g_diag[i];
    float loss = logf(g_sumexp[i]) - INV_TEMP * d;
    float pos  = d;
    float neg  = (g_sumS[i] - d) * (1.0f / (float)(B_SIZE - 1));

    #pragma unroll
    for (int off = 16; off; off >>= 1) {
        loss += __shfl_down_sync(0xffffffffu, loss, off);
        pos  += __shfl_down_sync(0xffffffffu, pos,  off);
        neg  += __shfl_down_sync(0xffffffffu, neg,  off);
    }
    __shared__ float sl[8], sp[8], sn[8];
    if (lane == 0) { sl[warp] = loss; sp[warp] = pos; sn[warp] = neg; }
    __syncthreads();
    if (threadIdx.x == 0) {
        float tl = 0.f, tp = 0.f, tg = 0.f;
        #pragma unroll
        for (int w = 0; w < 8; w++) { tl += sl[w]; tp += sp[w]; tg += sn[w]; }
        const float invB = 1.0f / (float)B_SIZE;
        atomicAdd(out + 0, tl * invB);
        atomicAdd(out + 1, tp * invB);
        atomicAdd(out + 2, tg * invB);
    }
}

// ---------------------------------------------------------------------------
extern "C" void kernel_launch(void* const* d_in, const int* in_sizes, int n_in,
                              void* d_out, int out_size) {
    const float* A = (const float*)d_in[0];
    const float* P = (const float*)d_in[1];
    float* out = (float*)d_out;

    cudaFuncSetAttribute(ntxent_hmma,
                         cudaFuncAttributeMaxDynamicSharedMemorySize, SMEM_BYTES);

    ntxent_zeroq<<<1, 1024>>>();
    ntxent_prep<<<B_SIZE / 8, 256>>>(A, P, out);
    ntxent_rowsum<<<B_SIZE / 8, 256>>>(A);

    dim3 gg(B_SIZE / BN, B_SIZE / BM);   // (64, 64)
    ntxent_hmma<<<gg, 128, SMEM_BYTES>>>();

    ntxent_finalize<<<B_SIZE / 256, 256>>>(out);
}

// round 13
// speedup vs baseline: 1.1837x; 1.0799x over previous
#include <cuda_runtime.h>
#include <cuda_bf16.h>
#include <math.h>
#include <stdint.h>

// NTXent — Round 13: best-of merge.
//  hmma: R8 verbatim (128x128 CTA, 4 warps of 64x64, BK=32, 3-stage
//        wait_group 1, refill AFTER compute, plain launch_bounds(128)).
//  overhead: fused qsum in prep; rowsum fused into finalize.

#define B_SIZE 8192
#define D_SIZE 626
#define KPAD   640
#define INV_TEMP 4.0f

#define BM 128
#define BN 128
#define BK 32
#define NITER (KPAD / BK)             // 20
#define STAGES 3
#define ROWB 80                        // 32 bf16 + 8B pad
#define STAGE_BYTES (2 * BM * ROWB)    // 20480
#define SMEM_BYTES (STAGES * STAGE_BYTES)   // 61440

// ---------------- persistent scratch ---------------------------------------
__device__ __align__(128) __nv_bfloat16 g_Ab[B_SIZE * KPAD];
__device__ __align__(128) __nv_bfloat16 g_Pb[B_SIZE * KPAD];
__device__ float g_rna[B_SIZE];
__device__ float g_sumexp[B_SIZE];
__device__ float g_diag[B_SIZE];
__device__ float g_q[D_SIZE];

// ---------------- helpers ---------------------------------------------------
__device__ __forceinline__ uint32_t smem_u32(const void* p) {
    uint32_t a;
    asm("{ .reg .u64 t; cvta.to.shared.u64 t, %1; cvt.u32.u64 %0, t; }"
        : "=r"(a) : "l"(p));
    return a;
}
__device__ __forceinline__ void cp16(uint32_t dst, const void* src) {
    asm volatile("cp.async.cg.shared.global [%0], [%1], 16;" :: "r"(dst), "l"(src));
}
__device__ __forceinline__ void ldsm_x4(uint32_t* r, uint32_t addr) {
    asm volatile("ldmatrix.sync.aligned.m8n8.x4.shared.b16 {%0,%1,%2,%3}, [%4];"
                 : "=r"(r[0]), "=r"(r[1]), "=r"(r[2]), "=r"(r[3]) : "r"(addr));
}
__device__ __forceinline__ void mma_bf16(float* c, const uint32_t* a,
                                         uint32_t b0, uint32_t b1) {
    asm volatile(
        "mma.sync.aligned.m16n8k16.row.col.f32.bf16.bf16.f32 "
        "{%0,%1,%2,%3}, {%4,%5,%6,%7}, {%8,%9}, {%0,%1,%2,%3};"
        : "+f"(c[0]), "+f"(c[1]), "+f"(c[2]), "+f"(c[3])
        : "r"(a[0]), "r"(a[1]), "r"(a[2]), "r"(a[3]), "r"(b0), "r"(b1));
}

// ---------------------------------------------------------------------------
// zeroq: reset global q accumulator (graph-replay safe)
// ---------------------------------------------------------------------------
__global__ void ntxent_zeroq() {
    if (threadIdx.x < D_SIZE) g_q[threadIdx.x] = 0.f;
}

// ---------------------------------------------------------------------------
// prep: norms, exact fp32 diag, normalized bf16 copies, fused q accumulation
// grid B/8, block 256; one warp per row
// ---------------------------------------------------------------------------
__global__ void __launch_bounds__(256) ntxent_prep(const float* __restrict__ A,
                                                   const float* __restrict__ P,
                                                   float* __restrict__ out) {
    __shared__ float qacc[D_SIZE];
    for (int c = threadIdx.x; c < D_SIZE; c += 256) qacc[c] = 0.f;
    __syncthreads();

    const int warp = threadIdx.x >> 5;
    const int lane = threadIdx.x & 31;
    const int row  = blockIdx.x * 8 + warp;

    const float* ar = A + (size_t)row * D_SIZE;
    const float* pr = P + (size_t)row * D_SIZE;
    float ssa = 0.f, ssp = 0.f, dot = 0.f;
    for (int c = lane; c < D_SIZE; c += 32) {
        float av = ar[c], pv = pr[c];
        ssa = fmaf(av, av, ssa);
        ssp = fmaf(pv, pv, ssp);
        dot = fmaf(av, pv, dot);
    }
    #pragma unroll
    for (int o = 16; o; o >>= 1) {
        ssa += __shfl_xor_sync(0xffffffffu, ssa, o);
        ssp += __shfl_xor_sync(0xffffffffu, ssp, o);
        dot += __shfl_xor_sync(0xffffffffu, dot, o);
    }
    const float rna = rsqrtf(ssa);
    const float rnp = rsqrtf(ssp);

    __nv_bfloat16* ya = g_Ab + (size_t)row * KPAD;
    __nv_bfloat16* yp = g_Pb + (size_t)row * KPAD;
    for (int c = lane; c < KPAD; c += 32) {
        float av = (c < D_SIZE) ? ar[c] * rna : 0.f;
        float pv = (c < D_SIZE) ? pr[c] * rnp : 0.f;
        ya[c] = __float2bfloat16(av);
        yp[c] = __float2bfloat16(pv);
        if (c < D_SIZE) atomicAdd(&qacc[c], pv);
    }
    if (lane == 0) {
        g_rna[row]    = rna;
        g_diag[row]   = dot * rna * rnp;
        g_sumexp[row] = 0.f;
    }
    __syncthreads();
    for (int c = threadIdx.x; c < D_SIZE; c += 256)
        atomicAdd(&g_q[c], qacc[c]);
    if (blockIdx.x == 0 && threadIdx.x < 3) out[threadIdx.x] = 0.f;
}

// ---------------------------------------------------------------------------
// stage loader (128 threads): 128x32 A + 128x32 B bf16, 16B cp.async each
// ---------------------------------------------------------------------------
__device__ __forceinline__ void load_stage(uint32_t sbase, int m0, int n0,
                                           int k0, int tid) {
    const char* asrc = (const char*)g_Ab + ((size_t)m0 * KPAD + k0) * 2;
    const char* bsrc = (const char*)g_Pb + ((size_t)n0 * KPAD + k0) * 2;
    #pragma unroll
    for (int i = 0; i < 4; i++) {
        int seg = tid + i * 128, row = seg >> 2, g = seg & 3;
        cp16(sbase + row * ROWB + g * 16, asrc + (size_t)row * (KPAD * 2) + g * 16);
    }
    #pragma unroll
    for (int i = 0; i < 4; i++) {
        int seg = tid + i * 128, row = seg >> 2, g = seg & 3;
        cp16(sbase + BM * ROWB + row * ROWB + g * 16,
             bsrc + (size_t)row * (KPAD * 2) + g * 16);
    }
    asm volatile("cp.async.commit_group;" ::: "memory");
}

// ---------------------------------------------------------------------------
// main: 128x128 tile, 4 warps (64x64), BK=32, 3-stage (wait_group 1),
// refill AFTER compute (R8 verbatim)
// ---------------------------------------------------------------------------
__global__ void __launch_bounds__(128) ntxent_hmma() {
    extern __shared__ char smem[];
    const uint32_t sbase = smem_u32(smem);

    const int tid  = threadIdx.x;
    const int lane = tid & 31;
    const int wid  = tid >> 5;
    const int wm   = wid >> 1;
    const int wn   = wid & 1;
    const int m0   = blockIdx.y * BM;
    const int n0   = blockIdx.x * BN;

    float acc[4][8][4];
    #pragma unroll
    for (int i = 0; i < 4; i++)
        #pragma unroll
        for (int j = 0; j < 8; j++)
            #pragma unroll
            for (int q = 0; q < 4; q++) acc[i][j][q] = 0.f;

    const int a_row  = lane & 15;
    const int a_koff = ((lane >> 4) & 1) * 16;
    const int b_n    = (lane & 7) | ((lane >> 1) & 8);
    const int b_koff = ((lane >> 3) & 1) * 16;
    const uint32_t aBase = sbase + (wm * 64 + a_row) * ROWB + a_koff;
    const uint32_t bBase = sbase + BM * ROWB + (wn * 64 + b_n) * ROWB + b_koff;

    load_stage(sbase,               m0, n0, 0,  tid);
    load_stage(sbase + STAGE_BYTES, m0, n0, BK, tid);

    uint32_t soff = 0;
    uint32_t loff = 2 * STAGE_BYTES;
    int      lk   = 2 * BK;

    for (int c = 0; c < NITER; c++) {
        if (c < NITER - 1) asm volatile("cp.async.wait_group 1;" ::: "memory");
        else               asm volatile("cp.async.wait_group 0;" ::: "memory");
        __syncthreads();

        #pragma unroll
        for (int ks = 0; ks < 2; ks++) {
            const uint32_t koff = soff + ks * 32;

            uint32_t afrag[4][4];
            #pragma unroll
            for (int mi = 0; mi < 4; mi++)
                ldsm_x4(afrag[mi], aBase + koff + mi * (16 * ROWB));

            uint32_t bfrag[4][4];
            #pragma unroll
            for (int np = 0; np < 4; np++)
                ldsm_x4(bfrag[np], bBase + koff + np * (16 * ROWB));

            #pragma unroll
            for (int mi = 0; mi < 4; mi++)
                #pragma unroll
                for (int np = 0; np < 4; np++) {
                    mma_bf16(acc[mi][np * 2 + 0], afrag[mi],
                             bfrag[np][0], bfrag[np][1]);
                    mma_bf16(acc[mi][np * 2 + 1], afrag[mi],
                             bfrag[np][2], bfrag[np][3]);
                }
        }

        if (c + 2 < NITER) {
            load_stage(sbase + loff, m0, n0, lk, tid);
            lk += BK;
            loff += STAGE_BYTES;
            if (loff == STAGES * STAGE_BYTES) loff = 0;
        }
        soff += STAGE_BYTES;
        if (soff == STAGES * STAGE_BYTES) soff = 0;
    }

    // ---- epilogue: per-row sum of exp(4*S) ----
    float esum[8];
    #pragma unroll
    for (int q = 0; q < 8; q++) esum[q] = 0.f;

    #pragma unroll
    for (int mi = 0; mi < 4; mi++)
        #pragma unroll
        for (int nt = 0; nt < 8; nt++) {
            const float* cc = acc[mi][nt];
            esum[mi * 2 + 0] += __expf(INV_TEMP * cc[0]) + __expf(INV_TEMP * cc[1]);
            esum[mi * 2 + 1] += __expf(INV_TEMP * cc[2]) + __expf(INV_TEMP * cc[3]);
        }
    #pragma unroll
    for (int q = 0; q < 8; q++)
        #pragma unroll
        for (int o = 1; o < 4; o <<= 1)
            esum[q] += __shfl_xor_sync(0xffffffffu, esum[q], o);
    if ((lane & 3) == 0) {
        #pragma unroll
        for (int q = 0; q < 8; q++) {
            const int row = m0 + wm * 64 + (q >> 1) * 16 + (q & 1) * 8 + (lane >> 2);
            atomicAdd(&g_sumexp[row], esum[q]);
        }
    }
}

// ---------------------------------------------------------------------------
// finalize (rowsum fused): one warp per row; block-reduce; atomicAdd to out
// grid B/8, block 256
// ---------------------------------------------------------------------------
__global__ void __launch_bounds__(256) ntxent_finalize(const float* __restrict__ A,
                                                       float* __restrict__ out) {
    const int warp = threadIdx.x >> 5;
    const int lane = threadIdx.x & 31;
    const int row  = blockIdx.x * 8 + warp;

    // rowsum_i = rna[i] * (A[i] . q)
    const float* ar = A + (size_t)row * D_SIZE;
    float d = 0.f;
    for (int c = lane; c < D_SIZE; c += 32)
        d = fmaf(ar[c], g_q[c], d);
    #pragma unroll
    for (int o = 16; o; o >>= 1) d += __shfl_xor_sync(0xffffffffu, d, o);

    float loss = 0.f, pos = 0.f, neg = 0.f;
    if (lane == 0) {
        const float diag = g_diag[row];
        const float sumS = d * g_rna[row];
        loss = logf(g_sumexp[row]) - INV_TEMP * diag;
        pos  = diag;
        neg  = (sumS - diag) * (1.0f / (float)(B_SIZE - 1));
    }

    __shared__ float sl[8], sp[8], sn[8];
    if (lane == 0) { sl[warp] = loss; sp[warp] = pos; sn[warp] = neg; }
    __syncthreads();
    if (threadIdx.x == 0) {
        float tl = 0.f, tp = 0.f, tg = 0.f;
        #pragma unroll
        for (int w = 0; w < 8; w++) { tl += sl[w]; tp += sp[w]; tg += sn[w]; }
        const float invB = 1.0f / (float)B_SIZE;
        atomicAdd(out + 0, tl * invB);
        atomicAdd(out + 1, tp * invB);
        atomicAdd(out + 2, tg * invB);
    }
}

// ---------------------------------------------------------------------------
extern "C" void kernel_launch(void* const* d_in, const int* in_sizes, int n_in,
                              void* d_out, int out_size) {
    const float* A = (const float*)d_in[0];
    const float* P = (const float*)d_in[1];
    float* out = (float*)d_out;

    cudaFuncSetAttribute(ntxent_hmma,
                         cudaFuncAttributeMaxDynamicSharedMemorySize, SMEM_BYTES);

    ntxent_zeroq<<<1, 1024>>>();
    ntxent_prep<<<B_SIZE / 8, 256>>>(A, P, out);

    dim3 gg(B_SIZE / BN, B_SIZE / BM);   // (64, 64)
    ntxent_hmma<<<gg, 128, SMEM_BYTES>>>();

    ntxent_finalize<<<B_SIZE / 8, 256>>>(A, out);
}